// round 2
// baseline (speedup 1.0000x reference)
#include <cuda_runtime.h>
#include <stdint.h>

// Problem constants (match reference_code)
#define NN   100000          // NU == NI
#define D    128
#define NFEAT (NN * D)       // 12.8M floats per array

// -----------------------------------------------------------------------------
// Scratch: static __device__ arrays (no allocations allowed).
//   which = 0 : etype ui (src=user proj W_ui, dst=item)
//   which = 1 : etype iu (src=item proj W_iu, dst=user)
//   which = 2 : etype uu (src=user proj W_uu, dst=user)
// -----------------------------------------------------------------------------
__device__ float g_Wh [3][NFEAT];   // projected src features per etype
__device__ float g_acc[3][NFEAT];   // per-dst sums per etype
__device__ float g_deg[3][NN];      // per-dst degrees per etype

// -----------------------------------------------------------------------------
// Zero accumulators + degrees (must run every launch: graph replays).
// -----------------------------------------------------------------------------
__global__ void zero_kernel() {
    const long stride = (long)gridDim.x * blockDim.x;
    long tid = (long)blockIdx.x * blockDim.x + threadIdx.x;

    float4* acc4 = reinterpret_cast<float4*>(&g_acc[0][0]);
    const long n4 = 3L * NFEAT / 4;
    for (long i = tid; i < n4; i += stride)
        acc4[i] = make_float4(0.f, 0.f, 0.f, 0.f);

    float* deg = &g_deg[0][0];
    for (long i = tid; i < 3L * NN; i += stride)
        deg[i] = 0.f;
}

// -----------------------------------------------------------------------------
// GEMM: C = A @ W + b,  A [N,128] row-major, W [128,128] row-major, C=g_Wh[which]
// Block tile 128x128 (full N-dim), BK=16, 256 threads, 8x8 strided register tile.
// -----------------------------------------------------------------------------
__global__ __launch_bounds__(256, 2)
void gemm_bias_kernel(const float* __restrict__ A,
                      const float* __restrict__ W,
                      const float* __restrict__ bias,
                      int which, int N)
{
    __shared__ float Ast[16][128];   // [k][m]
    __shared__ float Bs [16][128];   // [k][n]

    float* __restrict__ C = g_Wh[which];

    const int tid = threadIdx.x;
    const int tx  = tid & 15;        // n-group
    const int ty  = tid >> 4;        // m-group
    const int blockRow = blockIdx.x * 128;

    // A-load mapping: thread -> (row r, k-half)
    const int lr    = tid >> 1;      // 0..127
    const int lhalf = (tid & 1) * 8; // 0 or 8
    // B-load mapping: thread -> (k, n0)
    const int lk  = tid >> 4;        // 0..15
    const int ln0 = (tid & 15) * 8;  // 0..120

    float acc[8][8];
#pragma unroll
    for (int i = 0; i < 8; i++)
#pragma unroll
        for (int j = 0; j < 8; j++) acc[i][j] = 0.f;

    const int arow = blockRow + lr;
    const bool arow_ok = arow < N;

#pragma unroll 1
    for (int kt = 0; kt < 8; kt++) {
        // ---- load A tile (128 x 16), store transposed into Ast[k][m]
        float4 a0 = make_float4(0.f, 0.f, 0.f, 0.f);
        float4 a1 = a0;
        if (arow_ok) {
            const float* ap = A + (size_t)arow * 128 + kt * 16 + lhalf;
            a0 = *reinterpret_cast<const float4*>(ap);
            a1 = *reinterpret_cast<const float4*>(ap + 4);
        }
        Ast[lhalf + 0][lr] = a0.x;
        Ast[lhalf + 1][lr] = a0.y;
        Ast[lhalf + 2][lr] = a0.z;
        Ast[lhalf + 3][lr] = a0.w;
        Ast[lhalf + 4][lr] = a1.x;
        Ast[lhalf + 5][lr] = a1.y;
        Ast[lhalf + 6][lr] = a1.z;
        Ast[lhalf + 7][lr] = a1.w;

        // ---- load B tile (16 x 128)
        {
            const float* wp = W + (size_t)(kt * 16 + lk) * 128 + ln0;
            float4 b0 = *reinterpret_cast<const float4*>(wp);
            float4 b1 = *reinterpret_cast<const float4*>(wp + 4);
            *reinterpret_cast<float4*>(&Bs[lk][ln0])     = b0;
            *reinterpret_cast<float4*>(&Bs[lk][ln0 + 4]) = b1;
        }
        __syncthreads();

        // ---- compute
#pragma unroll
        for (int k = 0; k < 16; k++) {
            float a[8], b[8];
#pragma unroll
            for (int i = 0; i < 8; i++) a[i] = Ast[k][ty + i * 16];
#pragma unroll
            for (int j = 0; j < 8; j++) b[j] = Bs[k][tx + j * 16];
#pragma unroll
            for (int i = 0; i < 8; i++)
#pragma unroll
                for (int j = 0; j < 8; j++)
                    acc[i][j] += a[i] * b[j];
        }
        __syncthreads();
    }

    // ---- epilogue: add bias, store
    float bj[8];
#pragma unroll
    for (int j = 0; j < 8; j++) bj[j] = bias[tx + j * 16];

#pragma unroll
    for (int i = 0; i < 8; i++) {
        const int row = blockRow + ty + i * 16;
        if (row < N) {
            float* cp = C + (size_t)row * 128;
#pragma unroll
            for (int j = 0; j < 8; j++)
                cp[tx + j * 16] = acc[i][j] + bj[j];
        }
    }
}

// -----------------------------------------------------------------------------
// Scatter: one warp per edge; lane handles 4 contiguous features.
// Lane 0 also bumps the destination degree (fused degree pass).
// Grid-stride over edges so the grid size stays bounded.
// -----------------------------------------------------------------------------
__global__ __launch_bounds__(256)
void scatter_kernel(const int* __restrict__ src,
                    const int* __restrict__ dst,
                    int which, int E)
{
    const int lane   = threadIdx.x & 31;
    const int warp0  = (blockIdx.x * blockDim.x + threadIdx.x) >> 5;
    const int nwarps = (gridDim.x * blockDim.x) >> 5;

    const float* __restrict__ Wh = g_Wh[which];
    float*       __restrict__ ac = g_acc[which];
    float*       __restrict__ dg = g_deg[which];

    for (int e = warp0; e < E; e += nwarps) {
        const int s = src[e];
        const int d = dst[e];

        if (lane == 0)
            atomicAdd(&dg[d], 1.0f);

        float4 v = *reinterpret_cast<const float4*>(Wh + (size_t)s * 128 + lane * 4);
        float* a = ac + (size_t)d * 128 + lane * 4;
        atomicAdd(a + 0, v.x);
        atomicAdd(a + 1, v.y);
        atomicAdd(a + 2, v.z);
        atomicAdd(a + 3, v.w);
    }
}

// -----------------------------------------------------------------------------
// Finalize: out[0] = acc_iu/deg_iu + acc_uu/deg_uu ; out[1] = acc_ui/deg_ui.
// (acc==0 when deg==0, so dividing by max(deg,1) reproduces the where().)
// -----------------------------------------------------------------------------
__global__ void finalize_kernel(float* __restrict__ out)
{
    const long n4 = NFEAT / 4;
    const long stride = (long)gridDim.x * blockDim.x;
    float4* out_u = reinterpret_cast<float4*>(out);
    float4* out_i = reinterpret_cast<float4*>(out + (size_t)NFEAT);
    const float4* acc0 = reinterpret_cast<const float4*>(&g_acc[0][0]); // ui -> item
    const float4* acc1 = reinterpret_cast<const float4*>(&g_acc[1][0]); // iu -> user
    const float4* acc2 = reinterpret_cast<const float4*>(&g_acc[2][0]); // uu -> user

    for (long i = (long)blockIdx.x * blockDim.x + threadIdx.x; i < n4; i += stride) {
        const int n = (int)(i >> 5);   // i*4 / 128
        const float inv_ui = 1.0f / fmaxf(g_deg[0][n], 1.0f);
        const float inv_iu = 1.0f / fmaxf(g_deg[1][n], 1.0f);
        const float inv_uu = 1.0f / fmaxf(g_deg[2][n], 1.0f);

        float4 a1 = acc1[i], a2 = acc2[i], a0 = acc0[i];
        float4 u;
        u.x = a1.x * inv_iu + a2.x * inv_uu;
        u.y = a1.y * inv_iu + a2.y * inv_uu;
        u.z = a1.z * inv_iu + a2.z * inv_uu;
        u.w = a1.w * inv_iu + a2.w * inv_uu;
        out_u[i] = u;

        float4 it;
        it.x = a0.x * inv_ui;
        it.y = a0.y * inv_ui;
        it.z = a0.z * inv_ui;
        it.w = a0.w * inv_ui;
        out_i[i] = it;
    }
}

// -----------------------------------------------------------------------------
// kernel_launch
// -----------------------------------------------------------------------------
extern "C" void kernel_launch(void* const* d_in, const int* in_sizes, int n_in,
                              void* d_out, int out_size)
{
    const float* feat_user = (const float*)d_in[0];
    const float* feat_item = (const float*)d_in[1];
    const float* W_ui = (const float*)d_in[2];
    const float* b_ui = (const float*)d_in[3];
    const float* W_iu = (const float*)d_in[4];
    const float* b_iu = (const float*)d_in[5];
    const float* W_uu = (const float*)d_in[6];
    const float* b_uu = (const float*)d_in[7];
    const int* src_ui = (const int*)d_in[8];
    const int* dst_ui = (const int*)d_in[9];
    const int* src_iu = (const int*)d_in[10];
    const int* dst_iu = (const int*)d_in[11];
    const int* src_uu = (const int*)d_in[12];
    const int* dst_uu = (const int*)d_in[13];
    float* out = (float*)d_out;

    const int N = NN;
    const int E = in_sizes[8];

    // 1) zero accumulators/degrees
    zero_kernel<<<4096, 256>>>();

    // 2) three projections
    const int gemm_blocks = (N + 127) / 128;
    gemm_bias_kernel<<<gemm_blocks, 256>>>(feat_user, W_ui, b_ui, 0, N);
    gemm_bias_kernel<<<gemm_blocks, 256>>>(feat_item, W_iu, b_iu, 1, N);
    gemm_bias_kernel<<<gemm_blocks, 256>>>(feat_user, W_uu, b_uu, 2, N);

    // 3) scatter-add per etype (one warp per edge, degree fused on lane 0)
    int sblocks = (E * 32 + 255) / 256;
    if (sblocks > 65535) sblocks = 65535;
    scatter_kernel<<<sblocks, 256>>>(src_ui, dst_ui, 0, E);
    scatter_kernel<<<sblocks, 256>>>(src_iu, dst_iu, 1, E);
    scatter_kernel<<<sblocks, 256>>>(src_uu, dst_uu, 2, E);

    // 4) normalize + combine
    finalize_kernel<<<12500, 256>>>(out);
}

// round 5
// speedup vs baseline: 2.0216x; 2.0216x over previous
#include <cuda_runtime.h>
#include <stdint.h>

// Problem constants (match reference_code)
#define NN    100000          // NU == NI
#define D     128
#define NFEAT (NN * D)        // 12.8M floats per array
#define MAXE  600000
#define SCANB 512
#define NB    ((NN + SCANB - 1) / SCANB)   // scan blocks per etype = 196

// -----------------------------------------------------------------------------
// Scratch (static __device__; no allocations allowed).
//   etype 0 : ui (src=user proj W_ui, dst=item)
//   etype 1 : iu (src=item proj W_iu, dst=user)
//   etype 2 : uu (src=user proj W_uu, dst=user)
// -----------------------------------------------------------------------------
__device__ float g_Wh [3][NFEAT];       // projected src features per etype
__device__ int   g_cnt[3][NN];          // per-dst degree (int)
__device__ int   g_cur[3][NN];          // fill cursors
__device__ int   g_rs [3][NN];          // row start offsets (exclusive scan of cnt)
__device__ int   g_csr[3][MAXE];        // src indices bucketed by dst
__device__ int   g_part[3][NB];         // per-block partial sums for scan

// -----------------------------------------------------------------------------
// Zero the small integer buffers (every launch: graph replays).
// -----------------------------------------------------------------------------
__global__ __launch_bounds__(256)
void zero_small() {
    const int stride = gridDim.x * blockDim.x;
    int* c = &g_cnt[0][0];
    int* u = &g_cur[0][0];
    for (int i = blockIdx.x * blockDim.x + threadIdx.x; i < 3 * NN; i += stride) {
        c[i] = 0;
        u[i] = 0;
    }
}

// -----------------------------------------------------------------------------
// GEMM: C = A @ W + b. 128x128 block tile, BK=16, 256 threads, 8x8 reg tile,
// register-prefetch double buffering to hide global-load latency.
// -----------------------------------------------------------------------------
__global__ __launch_bounds__(256, 2)
void gemm_bias_kernel(const float* __restrict__ A,
                      const float* __restrict__ W,
                      const float* __restrict__ bias,
                      int which, int N)
{
    __shared__ float Ast[16][128];   // [k][m]
    __shared__ float Bs [16][128];   // [k][n]

    float* __restrict__ C = g_Wh[which];

    const int tid = threadIdx.x;
    const int tx  = tid & 15;        // n-group
    const int ty  = tid >> 4;        // m-group
    const int blockRow = blockIdx.x * 128;

    const int lr    = tid >> 1;      // A row within tile
    const int lhalf = (tid & 1) * 8; // A k-half
    const int lk  = tid >> 4;        // B k
    const int ln0 = (tid & 15) * 8;  // B n0

    float acc[8][8];
#pragma unroll
    for (int i = 0; i < 8; i++)
#pragma unroll
        for (int j = 0; j < 8; j++) acc[i][j] = 0.f;

    const int arow = blockRow + lr;
    const bool arow_ok = arow < N;

    const float4 z4 = make_float4(0.f, 0.f, 0.f, 0.f);
    float4 ra0 = z4, ra1 = z4, rb0, rb1;

    // prefetch tile 0
    if (arow_ok) {
        const float* ap = A + (size_t)arow * 128 + lhalf;
        ra0 = *reinterpret_cast<const float4*>(ap);
        ra1 = *reinterpret_cast<const float4*>(ap + 4);
    }
    {
        const float* wp = W + (size_t)lk * 128 + ln0;
        rb0 = *reinterpret_cast<const float4*>(wp);
        rb1 = *reinterpret_cast<const float4*>(wp + 4);
    }

#pragma unroll 1
    for (int kt = 0; kt < 8; kt++) {
        // ---- commit prefetched regs to smem
        Ast[lhalf + 0][lr] = ra0.x;
        Ast[lhalf + 1][lr] = ra0.y;
        Ast[lhalf + 2][lr] = ra0.z;
        Ast[lhalf + 3][lr] = ra0.w;
        Ast[lhalf + 4][lr] = ra1.x;
        Ast[lhalf + 5][lr] = ra1.y;
        Ast[lhalf + 6][lr] = ra1.z;
        Ast[lhalf + 7][lr] = ra1.w;
        *reinterpret_cast<float4*>(&Bs[lk][ln0])     = rb0;
        *reinterpret_cast<float4*>(&Bs[lk][ln0 + 4]) = rb1;
        __syncthreads();

        // ---- issue next tile's loads (latency hides under compute below)
        if (kt < 7) {
            if (arow_ok) {
                const float* ap = A + (size_t)arow * 128 + (kt + 1) * 16 + lhalf;
                ra0 = *reinterpret_cast<const float4*>(ap);
                ra1 = *reinterpret_cast<const float4*>(ap + 4);
            }
            const float* wp = W + (size_t)((kt + 1) * 16 + lk) * 128 + ln0;
            rb0 = *reinterpret_cast<const float4*>(wp);
            rb1 = *reinterpret_cast<const float4*>(wp + 4);
        }

        // ---- compute
#pragma unroll
        for (int k = 0; k < 16; k++) {
            float a[8], b[8];
#pragma unroll
            for (int i = 0; i < 8; i++) a[i] = Ast[k][ty + i * 16];
#pragma unroll
            for (int j = 0; j < 8; j++) b[j] = Bs[k][tx + j * 16];
#pragma unroll
            for (int i = 0; i < 8; i++)
#pragma unroll
                for (int j = 0; j < 8; j++)
                    acc[i][j] += a[i] * b[j];
        }
        __syncthreads();
    }

    float bj[8];
#pragma unroll
    for (int j = 0; j < 8; j++) bj[j] = bias[tx + j * 16];

#pragma unroll
    for (int i = 0; i < 8; i++) {
        const int row = blockRow + ty + i * 16;
        if (row < N) {
            float* cp = C + (size_t)row * 128;
#pragma unroll
            for (int j = 0; j < 8; j++)
                cp[tx + j * 16] = acc[i][j] + bj[j];
        }
    }
}

// -----------------------------------------------------------------------------
// CSR build step 1: degree histogram over all 3 etypes.
// -----------------------------------------------------------------------------
__global__ __launch_bounds__(256)
void hist_kernel(const int* __restrict__ dst0,
                 const int* __restrict__ dst1,
                 const int* __restrict__ dst2,
                 int E)
{
    const long total = 3L * E;
    const long stride = (long)gridDim.x * blockDim.x;
    for (long t = (long)blockIdx.x * blockDim.x + threadIdx.x; t < total; t += stride) {
        int et = (int)(t / E);
        int e  = (int)(t - (long)et * E);
        int d  = (et == 0) ? dst0[e] : (et == 1) ? dst1[e] : dst2[e];
        atomicAdd(&g_cnt[et][d], 1);
    }
}

// -----------------------------------------------------------------------------
// CSR build step 2a: per-block partial sums (grid = {NB, 3}, 512 threads).
// -----------------------------------------------------------------------------
__global__ __launch_bounds__(SCANB)
void scan_partials() {
    __shared__ int sh[SCANB];
    const int et = blockIdx.y;
    const int i  = blockIdx.x * SCANB + threadIdx.x;
    int v = (i < NN) ? g_cnt[et][i] : 0;
    sh[threadIdx.x] = v;
    __syncthreads();
    for (int s = SCANB / 2; s > 0; s >>= 1) {
        if (threadIdx.x < s) sh[threadIdx.x] += sh[threadIdx.x + s];
        __syncthreads();
    }
    if (threadIdx.x == 0) g_part[et][blockIdx.x] = sh[0];
}

// -----------------------------------------------------------------------------
// CSR build step 2b: exclusive-scan the block partials (1 block, 3 warps).
// -----------------------------------------------------------------------------
__global__ __launch_bounds__(128)
void scan_offsets() {
    const int warp = threadIdx.x >> 5;
    const int lane = threadIdx.x & 31;
    if (warp >= 3) return;
    int carry = 0;
    for (int base = 0; base < NB; base += 32) {
        const int idx = base + lane;
        int v = (idx < NB) ? g_part[warp][idx] : 0;
        int incl = v;
#pragma unroll
        for (int off = 1; off < 32; off <<= 1) {
            int n = __shfl_up_sync(0xffffffffu, incl, off);
            if (lane >= off) incl += n;
        }
        if (idx < NB) g_part[warp][idx] = carry + incl - v;
        carry += __shfl_sync(0xffffffffu, incl, 31);
    }
}

// -----------------------------------------------------------------------------
// CSR build step 2c: block exclusive scan + add block offset -> row starts.
// -----------------------------------------------------------------------------
__global__ __launch_bounds__(SCANB)
void scan_final() {
    __shared__ int sh[SCANB];
    const int et = blockIdx.y;
    const int t  = threadIdx.x;
    const int i  = blockIdx.x * SCANB + t;
    int v = (i < NN) ? g_cnt[et][i] : 0;
    sh[t] = v;
    __syncthreads();
    for (int off = 1; off < SCANB; off <<= 1) {
        int x = (t >= off) ? sh[t - off] : 0;
        __syncthreads();
        sh[t] += x;
        __syncthreads();
    }
    if (i < NN)
        g_rs[et][i] = g_part[et][blockIdx.x] + sh[t] - v;
}

// -----------------------------------------------------------------------------
// CSR build step 3: bucket src indices by dst.
// -----------------------------------------------------------------------------
__global__ __launch_bounds__(256)
void fill_kernel(const int* __restrict__ src0, const int* __restrict__ dst0,
                 const int* __restrict__ src1, const int* __restrict__ dst1,
                 const int* __restrict__ src2, const int* __restrict__ dst2,
                 int E)
{
    const long total = 3L * E;
    const long stride = (long)gridDim.x * blockDim.x;
    for (long t = (long)blockIdx.x * blockDim.x + threadIdx.x; t < total; t += stride) {
        int et = (int)(t / E);
        int e  = (int)(t - (long)et * E);
        int s, d;
        if (et == 0)      { s = src0[e]; d = dst0[e]; }
        else if (et == 1) { s = src1[e]; d = dst1[e]; }
        else              { s = src2[e]; d = dst2[e]; }
        int pos = atomicAdd(&g_cur[et][d], 1);
        g_csr[et][g_rs[et][d] + pos] = s;
    }
}

// -----------------------------------------------------------------------------
// Gather-reduce, one warp per dst node. Unrolled x4: batch-load 4 src indices,
// then issue 4 independent float4 loads (MLP), then accumulate.
// -----------------------------------------------------------------------------
__device__ __forceinline__ float4 gather_mean(const float* __restrict__ Wh,
                                              const int* __restrict__ csr,
                                              int start, int deg, int lane)
{
    float4 acc = make_float4(0.f, 0.f, 0.f, 0.f);
    int j = 0;
    for (; j + 3 < deg; j += 4) {
        int s0 = csr[start + j];
        int s1 = csr[start + j + 1];
        int s2 = csr[start + j + 2];
        int s3 = csr[start + j + 3];
        float4 v0 = *reinterpret_cast<const float4*>(Wh + (size_t)s0 * 128 + lane * 4);
        float4 v1 = *reinterpret_cast<const float4*>(Wh + (size_t)s1 * 128 + lane * 4);
        float4 v2 = *reinterpret_cast<const float4*>(Wh + (size_t)s2 * 128 + lane * 4);
        float4 v3 = *reinterpret_cast<const float4*>(Wh + (size_t)s3 * 128 + lane * 4);
        acc.x += (v0.x + v1.x) + (v2.x + v3.x);
        acc.y += (v0.y + v1.y) + (v2.y + v3.y);
        acc.z += (v0.z + v1.z) + (v2.z + v3.z);
        acc.w += (v0.w + v1.w) + (v2.w + v3.w);
    }
    for (; j < deg; j++) {
        int s0 = csr[start + j];
        float4 v0 = *reinterpret_cast<const float4*>(Wh + (size_t)s0 * 128 + lane * 4);
        acc.x += v0.x;
        acc.y += v0.y;
        acc.z += v0.z;
        acc.w += v0.w;
    }
    const float inv = (deg > 0) ? (1.0f / (float)deg) : 0.0f;
    acc.x *= inv; acc.y *= inv; acc.z *= inv; acc.w *= inv;
    return acc;
}

// item output: mean over etype 0 (ui)
__global__ __launch_bounds__(256)
void gather_item_kernel(float* __restrict__ out_i)
{
    const int warp = (blockIdx.x * blockDim.x + threadIdx.x) >> 5;
    const int lane = threadIdx.x & 31;
    if (warp >= NN) return;
    float4 r = gather_mean(g_Wh[0], g_csr[0], g_rs[0][warp], g_cnt[0][warp], lane);
    *reinterpret_cast<float4*>(out_i + (size_t)warp * 128 + lane * 4) = r;
}

// user output: mean over etype 1 (iu) + mean over etype 2 (uu)
__global__ __launch_bounds__(256)
void gather_user_kernel(float* __restrict__ out_u)
{
    const int warp = (blockIdx.x * blockDim.x + threadIdx.x) >> 5;
    const int lane = threadIdx.x & 31;
    if (warp >= NN) return;
    float4 a = gather_mean(g_Wh[1], g_csr[1], g_rs[1][warp], g_cnt[1][warp], lane);
    float4 b = gather_mean(g_Wh[2], g_csr[2], g_rs[2][warp], g_cnt[2][warp], lane);
    float4 r = make_float4(a.x + b.x, a.y + b.y, a.z + b.z, a.w + b.w);
    *reinterpret_cast<float4*>(out_u + (size_t)warp * 128 + lane * 4) = r;
}

// -----------------------------------------------------------------------------
// kernel_launch
// -----------------------------------------------------------------------------
extern "C" void kernel_launch(void* const* d_in, const int* in_sizes, int n_in,
                              void* d_out, int out_size)
{
    const float* feat_user = (const float*)d_in[0];
    const float* feat_item = (const float*)d_in[1];
    const float* W_ui = (const float*)d_in[2];
    const float* b_ui = (const float*)d_in[3];
    const float* W_iu = (const float*)d_in[4];
    const float* b_iu = (const float*)d_in[5];
    const float* W_uu = (const float*)d_in[6];
    const float* b_uu = (const float*)d_in[7];
    const int* src_ui = (const int*)d_in[8];
    const int* dst_ui = (const int*)d_in[9];
    const int* src_iu = (const int*)d_in[10];
    const int* dst_iu = (const int*)d_in[11];
    const int* src_uu = (const int*)d_in[12];
    const int* dst_uu = (const int*)d_in[13];
    float* out = (float*)d_out;

    const int N = NN;
    const int E = in_sizes[8];

    // 1) zero counters
    zero_small<<<1200, 256>>>();

    // 2) three projections
    const int gemm_blocks = (N + 127) / 128;
    gemm_bias_kernel<<<gemm_blocks, 256>>>(feat_user, W_ui, b_ui, 0, N);
    gemm_bias_kernel<<<gemm_blocks, 256>>>(feat_item, W_iu, b_iu, 1, N);
    gemm_bias_kernel<<<gemm_blocks, 256>>>(feat_user, W_uu, b_uu, 2, N);

    // 3) CSR build
    hist_kernel<<<2048, 256>>>(dst_ui, dst_iu, dst_uu, E);
    scan_partials<<<dim3(NB, 3), SCANB>>>();
    scan_offsets<<<1, 128>>>();
    scan_final<<<dim3(NB, 3), SCANB>>>();
    fill_kernel<<<2048, 256>>>(src_ui, dst_ui, src_iu, dst_iu, src_uu, dst_uu, E);

    // 4) gather-reduce directly into the output (mean + sum fused)
    const int gblocks = (NN * 32 + 255) / 256;
    gather_item_kernel<<<gblocks, 256>>>(out + (size_t)NFEAT);
    gather_user_kernel<<<gblocks, 256>>>(out);
}